// round 1
// baseline (speedup 1.0000x reference)
#include <cuda_runtime.h>
#include <math.h>

// ---------------- dimensions ----------------
#define N_IMG 17          // 16 exemplars (batch 0..15) + search (batch 16)
#define H0 383
#define W0 287
#define H0P 387           // pad 2
#define W0P 291
#define C1o 64
#define H1 95
#define W1 71
#define P1H 47
#define P1W 35
#define P1HP 51           // pad 2
#define P1WP 39
#define C2o 192
#define H2 47
#define W2 35
#define P2H 23
#define P2W 17
#define P2HP 25           // pad 1
#define P2WP 19
#define C3o 384
#define C4o 256
#define C5o 256
#define H5 23
#define W5 17
#define P5H 11
#define P5W 8
#define MM 88             // 11*8
#define DD 256
#define TT 16
#define TMN 1408          // TT*MM

// ---------------- scratch (device globals; no allocation) ----------------
__device__ float g_in [N_IMG*3*H0P*W0P];
__device__ float g_c1 [N_IMG*C1o*H1*W1];
__device__ float g_p1 [N_IMG*C1o*P1HP*P1WP];
__device__ float g_c2 [N_IMG*C2o*H2*W2];
__device__ float g_p2 [N_IMG*C2o*P2HP*P2WP];
__device__ float g_c3 [N_IMG*C3o*P2HP*P2WP];
__device__ float g_c4 [N_IMG*C4o*P2HP*P2WP];
__device__ float g_c5 [N_IMG*C5o*H5*W5];
__device__ float g_p5 [N_IMG*C5o*MM];
__device__ float g_xc [256*88];
__device__ float g_v  [256];
__device__ float g_xhat[256*88];
__device__ float g_nodes[TMN*256];
__device__ float g_Y1 [TMN*512];
__device__ float g_S  [16*512];
__device__ float g_h1 [TMN*512];
__device__ float g_Y2 [TMN*256];
__device__ float g_h2 [TMN*256];
__device__ float g_V1 [256*88];
__device__ float g_V1t[88*256];
__device__ float g_Vx [256*88];
__device__ float g_G  [256*88];
__device__ float g_Hh [256*88];
__device__ float g_A2 [88*88];
__device__ float g_xw [88*384];
__device__ float g_c1m[88*384];
__device__ float g_cw [88*256];
__device__ float g_V2t[88*256];

// ---------------- kernels ----------------

// copy raw images into pad-2 layout
__global__ void pad_copy_k(const float* __restrict__ src, float* __restrict__ dst,
                           int nimg, int boff)
{
    int idx = blockIdx.x * blockDim.x + threadIdx.x;
    int total = nimg * 3 * H0 * W0;
    if (idx >= total) return;
    int w = idx % W0; int t = idx / W0;
    int h = t % H0;   t /= H0;
    int c = t % 3;    int n = t / 3;
    dst[(((size_t)(boff + n) * 3 + c) * H0P + h + 2) * W0P + (w + 2)] = src[idx];
}

// direct conv + ReLU; input pre-padded so no bounds checks; 4 outputs/thread along W
template<int CIN, int K, int S>
__global__ __launch_bounds__(128)
void conv_relu_k(const float* __restrict__ in, const float* __restrict__ w,
                 const float* __restrict__ bias, float* __restrict__ out,
                 int Cout, int HinP, int WinP, int Hout, int Wout,
                 int HoutP, int WoutP, int opad)
{
    __shared__ float sw[CIN * K * K];
    int co = blockIdx.y % Cout;
    int n  = blockIdx.y / Cout;
    for (int i = threadIdx.x; i < CIN * K * K; i += blockDim.x)
        sw[i] = w[co * CIN * K * K + i];
    __syncthreads();

    int wq  = (Wout + 3) >> 2;
    int idx = blockIdx.x * blockDim.x + threadIdx.x;
    if (idx >= Hout * wq) return;
    int oh  = idx / wq;
    int ow0 = (idx % wq) * 4;

    float b = bias[co];
    float a0 = b, a1 = b, a2 = b, a3 = b;
    const float* inb = in + (size_t)n * CIN * HinP * WinP;
    for (int ci = 0; ci < CIN; ci++) {
        const float* ip = inb + (ci * HinP + oh * S) * WinP + ow0 * S;
        const float* wp = sw + ci * K * K;
        #pragma unroll
        for (int kh = 0; kh < K; kh++) {
            const float* r = ip + kh * WinP;
            #pragma unroll
            for (int kw = 0; kw < K; kw++) {
                float wv = wp[kh * K + kw];
                a0 += r[kw]         * wv;
                a1 += r[kw + S]     * wv;
                a2 += r[kw + 2 * S] * wv;
                a3 += r[kw + 3 * S] * wv;
            }
        }
    }
    float* op = out + ((size_t)(n * Cout + co) * HoutP + oh + opad) * WoutP + ow0 + opad;
    if (ow0 + 0 < Wout) op[0] = fmaxf(a0, 0.f);
    if (ow0 + 1 < Wout) op[1] = fmaxf(a1, 0.f);
    if (ow0 + 2 < Wout) op[2] = fmaxf(a2, 0.f);
    if (ow0 + 3 < Wout) op[3] = fmaxf(a3, 0.f);
}

// 3x3 stride-2 VALID maxpool, output written into (possibly padded) buffer
__global__ void maxpool_k(const float* __restrict__ in, float* __restrict__ out,
                          int NC, int Hin, int Win, int Ho, int Wo,
                          int HoP, int WoP, int opad)
{
    int idx = blockIdx.x * blockDim.x + threadIdx.x;
    int total = NC * Ho * Wo;
    if (idx >= total) return;
    int ow = idx % Wo; int t = idx / Wo;
    int oh = t % Ho;   int nc = t / Ho;
    const float* ip = in + ((size_t)nc * Hin + oh * 2) * Win + ow * 2;
    float m = -INFINITY;
    #pragma unroll
    for (int kh = 0; kh < 3; kh++)
        #pragma unroll
        for (int kw = 0; kw < 3; kw++)
            m = fmaxf(m, ip[kh * Win + kw]);
    out[((size_t)nc * HoP + oh + opad) * WoP + ow + opad] = m;
}

// conv1d(k=3,p=1) over Xf [256,88]
__global__ void cd_conv_k(const float* __restrict__ Xf, const float* __restrict__ wcd,
                          const float* __restrict__ bcd, float* __restrict__ xc)
{
    int p = blockIdx.x;     // 0..87
    int o = threadIdx.x;    // 0..255
    float acc = bcd[o];
    for (int i = 0; i < 256; i++) {
        const float* wr = wcd + (o * 256 + i) * 3;
        const float* xr = Xf + i * 88;
        if (p > 0)  acc += xr[p - 1] * wr[0];
        acc += xr[p] * wr[1];
        if (p < 87) acc += xr[p + 1] * wr[2];
    }
    xc[o * 88 + p] = acc;
}

__global__ void cd_max_k(const float* __restrict__ xc, float* __restrict__ v)
{
    int o = threadIdx.x;
    float m = -INFINITY;
    for (int p = 0; p < 88; p++) m = fmaxf(m, xc[o * 88 + p]);
    v[o] = m;
}

// X_hat[o,k] = sum_i v[i]*wt[i,o,k] + bt[o]
__global__ void xhat_k(const float* __restrict__ v, const float* __restrict__ wt,
                       const float* __restrict__ bt, float* __restrict__ xhat)
{
    __shared__ float sv[256];
    int o = blockIdx.x;     // 0..255
    int k = threadIdx.x;    // 0..87
    for (int i = threadIdx.x; i < 256; i += blockDim.x) sv[i] = v[i];
    __syncthreads();
    float acc = bt[o];
    for (int i = 0; i < 256; i++)
        acc += sv[i] * wt[((size_t)i * 256 + o) * 88 + k];
    xhat[o * 88 + k] = acc;
}

// nodes[m*16+t, d] = p5[t][d][m]
__global__ void gather_nodes_k(const float* __restrict__ p5, float* __restrict__ nodes)
{
    int idx = blockIdx.x * blockDim.x + threadIdx.x;
    if (idx >= TMN * 256) return;
    int d = idx % 256;
    int n = idx / 256;
    int t = n % 16, m = n / 16;
    nodes[idx] = p5[((size_t)t * 256 + d) * 88 + m];
}

// generic tiled SGEMM: C[M,N] = A[M,K] @ B[K,N]; flags: 1=bias/row, 2=bias/col, 4=lrelu
__global__ __launch_bounds__(256)
void sgemm_k(const float* __restrict__ A, const float* __restrict__ B,
             const float* __restrict__ bias, float* __restrict__ C,
             int M, int N, int K, int flags)
{
    __shared__ float As[16][16];
    __shared__ float Bs[16][17];
    int tx = threadIdx.x, ty = threadIdx.y;
    int row = blockIdx.y * 16 + ty;
    int col = blockIdx.x * 16 + tx;
    float acc = 0.f;
    for (int k0 = 0; k0 < K; k0 += 16) {
        As[ty][tx] = (row < M && k0 + tx < K) ? A[(size_t)row * K + k0 + tx] : 0.f;
        Bs[ty][tx] = (col < N && k0 + ty < K) ? B[(size_t)(k0 + ty) * N + col] : 0.f;
        __syncthreads();
        #pragma unroll
        for (int kk = 0; kk < 16; kk++) acc += As[ty][kk] * Bs[kk][tx];
        __syncthreads();
    }
    if (row < M && col < N) {
        if (flags & 1) acc += bias[row];
        if (flags & 2) acc += bias[col];
        if (flags & 4) acc = acc >= 0.f ? acc : 0.01f * acc;
        C[(size_t)row * N + col] = acc;
    }
}

// S[t,f] = sum_m Y[(m*16+t),f]
__global__ void a1_reduce_k(const float* __restrict__ Y, float* __restrict__ S, int F)
{
    int f = blockIdx.x * blockDim.x + threadIdx.x;
    int t = blockIdx.y;
    if (f >= F) return;
    float s = 0.f;
    for (int m = 0; m < 88; m++) s += Y[(size_t)(m * 16 + t) * F + f];
    S[t * F + f] = s;
}

// h[n,f] = lrelu(S[t,f] - (t==0)*Y[n,f] + bias[f])
__global__ void a1_apply_k(const float* __restrict__ Y, const float* __restrict__ S,
                           const float* __restrict__ bias, float* __restrict__ h, int F)
{
    int idx = blockIdx.x * blockDim.x + threadIdx.x;
    if (idx >= TMN * F) return;
    int f = idx % F;
    int n = idx / F;
    int t = n % 16;
    float val = S[t * F + f] + bias[f];
    if (t == 0) val -= Y[idx];
    h[idx] = val >= 0.f ? val : 0.01f * val;
}

// V1[d,m]=max_t h2[(m*16+t),d]; V1t[m,d]=V1; Vx = V1 + xhat
__global__ void v1_k(const float* __restrict__ h2, const float* __restrict__ xhat,
                     float* __restrict__ V1, float* __restrict__ V1t, float* __restrict__ Vx)
{
    int idx = blockIdx.x * blockDim.x + threadIdx.x;
    if (idx >= 256 * 88) return;
    int d = idx % 256;
    int m = idx / 256;
    float mx = -INFINITY;
    #pragma unroll
    for (int t = 0; t < 16; t++) mx = fmaxf(mx, h2[(size_t)(m * 16 + t) * 256 + d]);
    V1[d * 88 + m] = mx;
    V1t[m * 256 + d] = mx;
    Vx[d * 88 + m] = mx + xhat[d * 88 + m];
}

// A2[j,:] = softmax_i( sum_d Hh[d,j]*G[d,i] )
__global__ void attn_k(const float* __restrict__ G, const float* __restrict__ Hh,
                       float* __restrict__ A2)
{
    __shared__ float red[128];
    int j = blockIdx.x;
    int i = threadIdx.x;
    float s = 0.f;
    if (i < 88) {
        for (int d = 0; d < 256; d++) s += Hh[d * 88 + j] * G[d * 88 + i];
    }
    red[i] = (i < 88) ? s : -INFINITY;
    __syncthreads();
    for (int st = 64; st > 0; st >>= 1) {
        if (i < st) red[i] = fmaxf(red[i], red[i + st]);
        __syncthreads();
    }
    float mx = red[0];
    __syncthreads();
    float e = (i < 88) ? expf(s - mx) : 0.f;
    red[i] = e;
    __syncthreads();
    for (int st = 64; st > 0; st >>= 1) {
        if (i < st) red[i] += red[i + st];
        __syncthreads();
    }
    float sum = red[0];
    if (i < 88) A2[j * 88 + i] = e / sum;
}

// R = sum_{d,m} Xf[d,m] * V2t[m,d]
__global__ void final_dot_k(const float* __restrict__ Xf, const float* __restrict__ V2t,
                            float* __restrict__ out)
{
    __shared__ float red[256];
    float acc = 0.f;
    for (int e = threadIdx.x; e < 256 * 88; e += 256) {
        int d = e / 88, m = e % 88;
        acc += Xf[e] * V2t[m * 256 + d];
    }
    red[threadIdx.x] = acc;
    __syncthreads();
    for (int st = 128; st > 0; st >>= 1) {
        if (threadIdx.x < st) red[threadIdx.x] += red[threadIdx.x + st];
        __syncthreads();
    }
    if (threadIdx.x == 0) out[0] = red[0];
}

// ---------------- host ----------------
static float* symaddr(const void* s)
{
    void* p = nullptr;
    cudaGetSymbolAddress(&p, s);
    return (float*)p;
}

extern "C" void kernel_launch(void* const* d_in, const int* in_sizes, int n_in,
                              void* d_out, int out_size)
{
    const float* search    = (const float*)d_in[0];
    const float* exemplars = (const float*)d_in[1];
    const float* aw1 = (const float*)d_in[2];  const float* ab1 = (const float*)d_in[3];
    const float* aw2 = (const float*)d_in[4];  const float* ab2 = (const float*)d_in[5];
    const float* aw3 = (const float*)d_in[6];  const float* ab3 = (const float*)d_in[7];
    const float* aw4 = (const float*)d_in[8];  const float* ab4 = (const float*)d_in[9];
    const float* aw5 = (const float*)d_in[10]; const float* ab5 = (const float*)d_in[11];
    const float* wcd = (const float*)d_in[12]; const float* bcd = (const float*)d_in[13];
    const float* wt  = (const float*)d_in[14]; const float* bt  = (const float*)d_in[15];
    const float* ws1 = (const float*)d_in[16]; const float* bs1 = (const float*)d_in[17];
    const float* ws2 = (const float*)d_in[18]; const float* bs2 = (const float*)d_in[19];
    const float* wg  = (const float*)d_in[20]; const float* bg  = (const float*)d_in[21];
    const float* wh  = (const float*)d_in[22]; const float* bh  = (const float*)d_in[23];
    const float* wc1 = (const float*)d_in[24]; const float* bc1 = (const float*)d_in[25];
    const float* wc2 = (const float*)d_in[26]; const float* bc2 = (const float*)d_in[27];

    float* p_in  = symaddr(g_in);
    float* p_c1  = symaddr(g_c1);
    float* p_p1  = symaddr(g_p1);
    float* p_c2  = symaddr(g_c2);
    float* p_p2  = symaddr(g_p2);
    float* p_c3  = symaddr(g_c3);
    float* p_c4  = symaddr(g_c4);
    float* p_c5  = symaddr(g_c5);
    float* p_p5  = symaddr(g_p5);
    float* p_xc  = symaddr(g_xc);
    float* p_v   = symaddr(g_v);
    float* p_xh  = symaddr(g_xhat);
    float* p_nd  = symaddr(g_nodes);
    float* p_Y1  = symaddr(g_Y1);
    float* p_S   = symaddr(g_S);
    float* p_h1  = symaddr(g_h1);
    float* p_Y2  = symaddr(g_Y2);
    float* p_h2  = symaddr(g_h2);
    float* p_V1  = symaddr(g_V1);
    float* p_V1t = symaddr(g_V1t);
    float* p_Vx  = symaddr(g_Vx);
    float* p_G   = symaddr(g_G);
    float* p_Hh  = symaddr(g_Hh);
    float* p_A2  = symaddr(g_A2);
    float* p_xw  = symaddr(g_xw);
    float* p_c1m = symaddr(g_c1m);
    float* p_cw  = symaddr(g_cw);
    float* p_V2t = symaddr(g_V2t);

    // zero padded buffers (borders must be 0 every replay)
    cudaMemsetAsync(p_in, 0, sizeof(float) * (size_t)N_IMG * 3 * H0P * W0P, 0);
    cudaMemsetAsync(p_p1, 0, sizeof(float) * (size_t)N_IMG * C1o * P1HP * P1WP, 0);
    cudaMemsetAsync(p_p2, 0, sizeof(float) * (size_t)N_IMG * C2o * P2HP * P2WP, 0);
    cudaMemsetAsync(p_c3, 0, sizeof(float) * (size_t)N_IMG * C3o * P2HP * P2WP, 0);
    cudaMemsetAsync(p_c4, 0, sizeof(float) * (size_t)N_IMG * C4o * P2HP * P2WP, 0);

    // assemble padded input batch: exemplars first (0..15), search last (16)
    {
        int tot = 16 * 3 * H0 * W0;
        pad_copy_k<<<(tot + 127) / 128, 128>>>(exemplars, p_in, 16, 0);
        tot = 3 * H0 * W0;
        pad_copy_k<<<(tot + 127) / 128, 128>>>(search, p_in, 1, 16);
    }

    // ---- AlexNet features ----
    {   // conv1: 3->64, k11 s4, in padded2
        int wq = (W1 + 3) / 4, sp = H1 * wq;
        conv_relu_k<3, 11, 4><<<dim3((sp + 127) / 128, N_IMG * C1o), 128>>>(
            p_in, aw1, ab1, p_c1, C1o, H0P, W0P, H1, W1, H1, W1, 0);
    }
    {   // pool1 -> padded2 buffer
        int tot = N_IMG * C1o * P1H * P1W;
        maxpool_k<<<(tot + 127) / 128, 128>>>(p_c1, p_p1, N_IMG * C1o, H1, W1, P1H, P1W, P1HP, P1WP, 2);
    }
    {   // conv2: 64->192, k5 s1
        int wq = (W2 + 3) / 4, sp = H2 * wq;
        conv_relu_k<64, 5, 1><<<dim3((sp + 127) / 128, N_IMG * C2o), 128>>>(
            p_p1, aw2, ab2, p_c2, C2o, P1HP, P1WP, H2, W2, H2, W2, 0);
    }
    {   // pool2 -> padded1 buffer
        int tot = N_IMG * C2o * P2H * P2W;
        maxpool_k<<<(tot + 127) / 128, 128>>>(p_c2, p_p2, N_IMG * C2o, H2, W2, P2H, P2W, P2HP, P2WP, 1);
    }
    {   // conv3: 192->384, out padded1
        int wq = (P2W + 3) / 4, sp = P2H * wq;
        conv_relu_k<192, 3, 1><<<dim3((sp + 127) / 128, N_IMG * C3o), 128>>>(
            p_p2, aw3, ab3, p_c3, C3o, P2HP, P2WP, P2H, P2W, P2HP, P2WP, 1);
    }
    {   // conv4: 384->256, out padded1
        int wq = (P2W + 3) / 4, sp = P2H * wq;
        conv_relu_k<384, 3, 1><<<dim3((sp + 127) / 128, N_IMG * C4o), 128>>>(
            p_c3, aw4, ab4, p_c4, C4o, P2HP, P2WP, P2H, P2W, P2HP, P2WP, 1);
    }
    {   // conv5: 256->256, out unpadded
        int wq = (P2W + 3) / 4, sp = P2H * wq;
        conv_relu_k<256, 3, 1><<<dim3((sp + 127) / 128, N_IMG * C5o), 128>>>(
            p_c4, aw5, ab5, p_c5, C5o, P2HP, P2WP, H5, W5, H5, W5, 0);
    }
    {   // pool5 -> [17,256,11,8]
        int tot = N_IMG * C5o * P5H * P5W;
        maxpool_k<<<(tot + 127) / 128, 128>>>(p_c5, p_p5, N_IMG * C5o, H5, W5, P5H, P5W, P5H, P5W, 0);
    }

    const float* Xf = p_p5 + (size_t)16 * 256 * 88;   // search features [256,88]

    // ---- conv_deconv branch ----
    cd_conv_k<<<88, 256>>>(Xf, wcd, bcd, p_xc);
    cd_max_k<<<1, 256>>>(p_xc, p_v);
    xhat_k<<<256, 88>>>(p_v, wt, bt, p_xh);

    // ---- spatiotemporal GCN ----
    gather_nodes_k<<<(TMN * 256 + 127) / 128, 128>>>(p_p5, p_nd);
    sgemm_k<<<dim3(512 / 16, TMN / 16), dim3(16, 16)>>>(p_nd, ws1, nullptr, p_Y1, TMN, 512, 256, 0);
    a1_reduce_k<<<dim3(4, 16), 128>>>(p_Y1, p_S, 512);
    a1_apply_k<<<(TMN * 512 + 255) / 256, 256>>>(p_Y1, p_S, bs1, p_h1, 512);
    sgemm_k<<<dim3(256 / 16, TMN / 16), dim3(16, 16)>>>(p_h1, ws2, nullptr, p_Y2, TMN, 256, 512, 0);
    a1_reduce_k<<<dim3(2, 16), 128>>>(p_Y2, p_S, 256);
    a1_apply_k<<<(TMN * 256 + 255) / 256, 256>>>(p_Y2, p_S, bs2, p_h2, 256);
    v1_k<<<(256 * 88 + 255) / 256, 256>>>(p_h2, p_xh, p_V1, p_V1t, p_Vx);

    // ---- dynamic cross-track graph ----
    sgemm_k<<<dim3((88 + 15) / 16, 16), dim3(16, 16)>>>(wg, p_Vx, bg, p_G, 256, 88, 256, 1);
    sgemm_k<<<dim3((88 + 15) / 16, 16), dim3(16, 16)>>>(wh, p_Vx, bh, p_Hh, 256, 88, 256, 1);
    attn_k<<<88, 128>>>(p_G, p_Hh, p_A2);

    // ---- ct GCN ----
    sgemm_k<<<dim3(384 / 16, (88 + 15) / 16), dim3(16, 16)>>>(p_V1t, wc1, nullptr, p_xw, 88, 384, 256, 0);
    sgemm_k<<<dim3(384 / 16, (88 + 15) / 16), dim3(16, 16)>>>(p_A2, p_xw, bc1, p_c1m, 88, 384, 88, 2 | 4);
    sgemm_k<<<dim3(256 / 16, (88 + 15) / 16), dim3(16, 16)>>>(p_c1m, wc2, nullptr, p_cw, 88, 256, 384, 0);
    sgemm_k<<<dim3(256 / 16, (88 + 15) / 16), dim3(16, 16)>>>(p_A2, p_cw, bc2, p_V2t, 88, 256, 88, 2 | 4);

    // ---- final correlation ----
    final_dot_k<<<1, 256>>>(Xf, p_V2t, (float*)d_out);
}

// round 2
// speedup vs baseline: 2.6720x; 2.6720x over previous
#include <cuda_runtime.h>
#include <math.h>

// ---------------- dimensions ----------------
#define N_IMG 17          // 16 exemplars (batch 0..15) + search (batch 16)
#define H0 383
#define W0 287
#define H0P 387           // pad 2
#define W0P 291
#define C1o 64
#define H1 95
#define W1 71
#define P1H 47
#define P1W 35
#define P1HP 51           // pad 2
#define P1WP 39
#define C2o 192
#define H2 47
#define W2 35
#define P2H 23
#define P2W 17
#define P2HP 25           // pad 1
#define P2WP 19
#define C3o 384
#define C4o 256
#define C5o 256
#define H5 23
#define W5 17
#define P5H 11
#define P5W 8
#define MM 88             // 11*8
#define DD 256
#define TT 16
#define TMN 1408          // TT*MM
#define TAILPAD 4096      // over-read safety pad on conv input buffers

// ---------------- scratch (device globals; no allocation) ----------------
__device__ float g_in [N_IMG*3*H0P*W0P + TAILPAD];
__device__ float g_c1 [N_IMG*C1o*H1*W1];
__device__ float g_p1 [N_IMG*C1o*P1HP*P1WP + TAILPAD];
__device__ float g_c2 [N_IMG*C2o*H2*W2];
__device__ float g_p2 [N_IMG*C2o*P2HP*P2WP + TAILPAD];
__device__ float g_c3 [N_IMG*C3o*P2HP*P2WP + TAILPAD];
__device__ float g_c4 [N_IMG*C4o*P2HP*P2WP + TAILPAD];
__device__ float g_c5 [N_IMG*C5o*H5*W5];
__device__ float g_p5 [N_IMG*C5o*MM];
__device__ float g_xc [256*88];
__device__ float g_v  [256];
__device__ float g_xhat[256*88];
__device__ float g_nodes[TMN*256];
__device__ float g_Y1 [TMN*512];
__device__ float g_S  [16*512];
__device__ float g_h1 [TMN*512];
__device__ float g_Y2 [TMN*256];
__device__ float g_h2 [TMN*256];
__device__ float g_V1 [256*88];
__device__ float g_V1t[88*256];
__device__ float g_Vx [256*88];
__device__ float g_G  [256*88];
__device__ float g_Hh [256*88];
__device__ float g_A2 [88*88];
__device__ float g_xw [88*384];
__device__ float g_c1m[88*384];
__device__ float g_cw [88*256];
__device__ float g_V2t[88*256];

// ---------------- kernels ----------------

// copy raw images into pad-2 layout
__global__ void pad_copy_k(const float* __restrict__ src, float* __restrict__ dst,
                           int nimg, int boff)
{
    int idx = blockIdx.x * blockDim.x + threadIdx.x;
    int total = nimg * 3 * H0 * W0;
    if (idx >= total) return;
    int w = idx % W0; int t = idx / W0;
    int h = t % H0;   t /= H0;
    int c = t % 3;    int n = t / 3;
    dst[(((size_t)(boff + n) * 3 + c) * H0P + h + 2) * W0P + (w + 2)] = src[idx];
}

// Direct conv + ReLU, register-blocked: 4 output channels x 4 output cols per
// thread. Weights for the 4-channel group staged in SMEM in CIC-channel chunks
// (broadcast reads). Input pre-padded -> no bounds checks inside the hot loop.
template<int CIN, int K, int S, int CIC>
__global__ __launch_bounds__(128)
void conv4x4_k(const float* __restrict__ in, const float* __restrict__ w,
               const float* __restrict__ bias, float* __restrict__ out,
               int Cout, int HinP, int WinP, int Hout, int Wout,
               int HoP, int WoP, int opad)
{
    constexpr int KK = K * K;
    constexpr int RW = K + 3 * S;       // input row width per thread
    __shared__ float sw[CIC * 4 * KK];

    int cg  = blockIdx.y % (Cout >> 2);
    int n   = blockIdx.y / (Cout >> 2);
    int co0 = cg << 2;

    int wq  = (Wout + 3) >> 2;
    int idx = blockIdx.x * blockDim.x + threadIdx.x;
    bool active = idx < Hout * wq;
    int oh  = active ? idx / wq : 0;
    int ow0 = active ? (idx % wq) << 2 : 0;

    float acc[4][4];
    #pragma unroll
    for (int c = 0; c < 4; c++) {
        float b = bias[co0 + c];
        #pragma unroll
        for (int x = 0; x < 4; x++) acc[c][x] = b;
    }

    const float* inb = in + (size_t)n * CIN * HinP * WinP
                          + (size_t)(oh * S) * WinP + ow0 * S;

    for (int c0 = 0; c0 < CIN; c0 += CIC) {
        // stage weights for this ci-chunk, 4 output channels
        for (int i = threadIdx.x; i < CIC * 4 * KK; i += 128) {
            int kk = i % KK;
            int t  = i / KK;
            int c  = t & 3;
            int ci = t >> 2;
            sw[i] = w[((size_t)(co0 + c) * CIN + c0 + ci) * KK + kk];
        }
        __syncthreads();

        if (active) {
            const float* ipc = inb + (size_t)c0 * HinP * WinP;
            for (int ci = 0; ci < CIC; ci++) {
                const float* ip = ipc + (size_t)ci * HinP * WinP;
                const float* wp = sw + ci * 4 * KK;
                #pragma unroll
                for (int kh = 0; kh < K; kh++) {
                    float r[RW];
                    const float* row = ip + kh * WinP;
                    #pragma unroll
                    for (int j = 0; j < RW; j++) r[j] = row[j];
                    #pragma unroll
                    for (int kw = 0; kw < K; kw++) {
                        float w0 = wp[0 * KK + kh * K + kw];
                        float w1 = wp[1 * KK + kh * K + kw];
                        float w2 = wp[2 * KK + kh * K + kw];
                        float w3 = wp[3 * KK + kh * K + kw];
                        #pragma unroll
                        for (int x = 0; x < 4; x++) {
                            float xv = r[kw + x * S];
                            acc[0][x] += xv * w0;
                            acc[1][x] += xv * w1;
                            acc[2][x] += xv * w2;
                            acc[3][x] += xv * w3;
                        }
                    }
                }
            }
        }
        __syncthreads();
    }

    if (!active) return;
    #pragma unroll
    for (int c = 0; c < 4; c++) {
        float* op = out + ((size_t)(n * Cout + co0 + c) * HoP + oh + opad) * WoP
                        + ow0 + opad;
        #pragma unroll
        for (int x = 0; x < 4; x++)
            if (ow0 + x < Wout) op[x] = fmaxf(acc[c][x], 0.f);
    }
}

// 3x3 stride-2 VALID maxpool, output written into (possibly padded) buffer
__global__ void maxpool_k(const float* __restrict__ in, float* __restrict__ out,
                          int NC, int Hin, int Win, int Ho, int Wo,
                          int HoP, int WoP, int opad)
{
    int idx = blockIdx.x * blockDim.x + threadIdx.x;
    int total = NC * Ho * Wo;
    if (idx >= total) return;
    int ow = idx % Wo; int t = idx / Wo;
    int oh = t % Ho;   int nc = t / Ho;
    const float* ip = in + ((size_t)nc * Hin + oh * 2) * Win + ow * 2;
    float m = -INFINITY;
    #pragma unroll
    for (int kh = 0; kh < 3; kh++)
        #pragma unroll
        for (int kw = 0; kw < 3; kw++)
            m = fmaxf(m, ip[kh * Win + kw]);
    out[((size_t)nc * HoP + oh + opad) * WoP + ow + opad] = m;
}

// conv1d(k=3,p=1) over Xf [256,88]
__global__ void cd_conv_k(const float* __restrict__ Xf, const float* __restrict__ wcd,
                          const float* __restrict__ bcd, float* __restrict__ xc)
{
    int p = blockIdx.x;     // 0..87
    int o = threadIdx.x;    // 0..255
    float acc = bcd[o];
    for (int i = 0; i < 256; i++) {
        const float* wr = wcd + (o * 256 + i) * 3;
        const float* xr = Xf + i * 88;
        if (p > 0)  acc += xr[p - 1] * wr[0];
        acc += xr[p] * wr[1];
        if (p < 87) acc += xr[p + 1] * wr[2];
    }
    xc[o * 88 + p] = acc;
}

__global__ void cd_max_k(const float* __restrict__ xc, float* __restrict__ v)
{
    int o = threadIdx.x;
    float m = -INFINITY;
    for (int p = 0; p < 88; p++) m = fmaxf(m, xc[o * 88 + p]);
    v[o] = m;
}

// X_hat[o,k] = sum_i v[i]*wt[i,o,k] + bt[o]
__global__ void xhat_k(const float* __restrict__ v, const float* __restrict__ wt,
                       const float* __restrict__ bt, float* __restrict__ xhat)
{
    __shared__ float sv[256];
    int o = blockIdx.x;     // 0..255
    int k = threadIdx.x;    // 0..87
    for (int i = threadIdx.x; i < 256; i += blockDim.x) sv[i] = v[i];
    __syncthreads();
    float acc = bt[o];
    for (int i = 0; i < 256; i++)
        acc += sv[i] * wt[((size_t)i * 256 + o) * 88 + k];
    xhat[o * 88 + k] = acc;
}

// nodes[m*16+t, d] = p5[t][d][m]
__global__ void gather_nodes_k(const float* __restrict__ p5, float* __restrict__ nodes)
{
    int idx = blockIdx.x * blockDim.x + threadIdx.x;
    if (idx >= TMN * 256) return;
    int d = idx % 256;
    int n = idx / 256;
    int t = n % 16, m = n / 16;
    nodes[idx] = p5[((size_t)t * 256 + d) * 88 + m];
}

// register-blocked SGEMM: C[M,N] = A[M,K] @ B[K,N]
// 64x64 block tile, 4x4 per thread, 256 threads, k-tile 16.
// flags: 1=bias per row, 2=bias per col, 4=leaky relu
__global__ __launch_bounds__(256)
void rbgemm_k(const float* __restrict__ A, const float* __restrict__ B,
              const float* __restrict__ bias, float* __restrict__ C,
              int M, int N, int K, int flags)
{
    __shared__ float As[16][65];
    __shared__ float Bs[16][64];
    int tid = threadIdx.x;
    int tx = tid & 15;          // 0..15 -> N
    int ty = tid >> 4;          // 0..15 -> M
    int m0 = blockIdx.y * 64;
    int n0 = blockIdx.x * 64;

    float acc[4][4] = {};

    for (int k0 = 0; k0 < K; k0 += 16) {
        // load A tile: elem e = tid + i*256; kk = e%16, mm = e/16
        #pragma unroll
        for (int i = 0; i < 4; i++) {
            int e  = tid + i * 256;
            int kk = e & 15;
            int mm = e >> 4;
            int gm = m0 + mm, gk = k0 + kk;
            As[kk][mm] = (gm < M && gk < K) ? A[(size_t)gm * K + gk] : 0.f;
        }
        // load B tile: nn = tid%64, kk = tid/64 + 4*i
        #pragma unroll
        for (int i = 0; i < 4; i++) {
            int nn = tid & 63;
            int kk = (tid >> 6) + i * 4;
            int gk = k0 + kk, gn = n0 + nn;
            Bs[kk][nn] = (gk < K && gn < N) ? B[(size_t)gk * N + gn] : 0.f;
        }
        __syncthreads();
        #pragma unroll
        for (int kk = 0; kk < 16; kk++) {
            float ra[4], rb[4];
            #pragma unroll
            for (int i = 0; i < 4; i++) ra[i] = As[kk][ty * 4 + i];
            #pragma unroll
            for (int j = 0; j < 4; j++) rb[j] = Bs[kk][tx * 4 + j];
            #pragma unroll
            for (int i = 0; i < 4; i++)
                #pragma unroll
                for (int j = 0; j < 4; j++)
                    acc[i][j] += ra[i] * rb[j];
        }
        __syncthreads();
    }

    #pragma unroll
    for (int i = 0; i < 4; i++) {
        int gm = m0 + ty * 4 + i;
        if (gm >= M) continue;
        #pragma unroll
        for (int j = 0; j < 4; j++) {
            int gn = n0 + tx * 4 + j;
            if (gn >= N) continue;
            float v = acc[i][j];
            if (flags & 1) v += bias[gm];
            if (flags & 2) v += bias[gn];
            if (flags & 4) v = v >= 0.f ? v : 0.01f * v;
            C[(size_t)gm * N + gn] = v;
        }
    }
}

// S[t,f] = sum_m Y[(m*16+t),f]
__global__ void a1_reduce_k(const float* __restrict__ Y, float* __restrict__ S, int F)
{
    int f = blockIdx.x * blockDim.x + threadIdx.x;
    int t = blockIdx.y;
    if (f >= F) return;
    float s = 0.f;
    for (int m = 0; m < 88; m++) s += Y[(size_t)(m * 16 + t) * F + f];
    S[t * F + f] = s;
}

// h[n,f] = lrelu(S[t,f] - (t==0)*Y[n,f] + bias[f])
__global__ void a1_apply_k(const float* __restrict__ Y, const float* __restrict__ S,
                           const float* __restrict__ bias, float* __restrict__ h, int F)
{
    int idx = blockIdx.x * blockDim.x + threadIdx.x;
    if (idx >= TMN * F) return;
    int f = idx % F;
    int n = idx / F;
    int t = n % 16;
    float val = S[t * F + f] + bias[f];
    if (t == 0) val -= Y[idx];
    h[idx] = val >= 0.f ? val : 0.01f * val;
}

// V1[d,m]=max_t h2[(m*16+t),d]; V1t[m,d]=V1; Vx = V1 + xhat
__global__ void v1_k(const float* __restrict__ h2, const float* __restrict__ xhat,
                     float* __restrict__ V1, float* __restrict__ V1t, float* __restrict__ Vx)
{
    int idx = blockIdx.x * blockDim.x + threadIdx.x;
    if (idx >= 256 * 88) return;
    int d = idx % 256;
    int m = idx / 256;
    float mx = -INFINITY;
    #pragma unroll
    for (int t = 0; t < 16; t++) mx = fmaxf(mx, h2[(size_t)(m * 16 + t) * 256 + d]);
    V1[d * 88 + m] = mx;
    V1t[m * 256 + d] = mx;
    Vx[d * 88 + m] = mx + xhat[d * 88 + m];
}

// A2[j,:] = softmax_i( sum_d Hh[d,j]*G[d,i] )
__global__ void attn_k(const float* __restrict__ G, const float* __restrict__ Hh,
                       float* __restrict__ A2)
{
    __shared__ float red[128];
    int j = blockIdx.x;
    int i = threadIdx.x;
    float s = 0.f;
    if (i < 88) {
        for (int d = 0; d < 256; d++) s += Hh[d * 88 + j] * G[d * 88 + i];
    }
    red[i] = (i < 88) ? s : -INFINITY;
    __syncthreads();
    for (int st = 64; st > 0; st >>= 1) {
        if (i < st) red[i] = fmaxf(red[i], red[i + st]);
        __syncthreads();
    }
    float mx = red[0];
    __syncthreads();
    float e = (i < 88) ? expf(s - mx) : 0.f;
    red[i] = e;
    __syncthreads();
    for (int st = 64; st > 0; st >>= 1) {
        if (i < st) red[i] += red[i + st];
        __syncthreads();
    }
    float sum = red[0];
    if (i < 88) A2[j * 88 + i] = e / sum;
}

// R = sum_{d,m} Xf[d,m] * V2t[m,d]
__global__ void final_dot_k(const float* __restrict__ Xf, const float* __restrict__ V2t,
                            float* __restrict__ out)
{
    __shared__ float red[256];
    float acc = 0.f;
    for (int e = threadIdx.x; e < 256 * 88; e += 256) {
        int d = e / 88, m = e % 88;
        acc += Xf[e] * V2t[m * 256 + d];
    }
    red[threadIdx.x] = acc;
    __syncthreads();
    for (int st = 128; st > 0; st >>= 1) {
        if (threadIdx.x < st) red[threadIdx.x] += red[threadIdx.x + st];
        __syncthreads();
    }
    if (threadIdx.x == 0) out[0] = red[0];
}

// ---------------- host ----------------
static float* symaddr(const void* s)
{
    void* p = nullptr;
    cudaGetSymbolAddress(&p, s);
    return (float*)p;
}

extern "C" void kernel_launch(void* const* d_in, const int* in_sizes, int n_in,
                              void* d_out, int out_size)
{
    const float* search    = (const float*)d_in[0];
    const float* exemplars = (const float*)d_in[1];
    const float* aw1 = (const float*)d_in[2];  const float* ab1 = (const float*)d_in[3];
    const float* aw2 = (const float*)d_in[4];  const float* ab2 = (const float*)d_in[5];
    const float* aw3 = (const float*)d_in[6];  const float* ab3 = (const float*)d_in[7];
    const float* aw4 = (const float*)d_in[8];  const float* ab4 = (const float*)d_in[9];
    const float* aw5 = (const float*)d_in[10]; const float* ab5 = (const float*)d_in[11];
    const float* wcd = (const float*)d_in[12]; const float* bcd = (const float*)d_in[13];
    const float* wt  = (const float*)d_in[14]; const float* bt  = (const float*)d_in[15];
    const float* ws1 = (const float*)d_in[16]; const float* bs1 = (const float*)d_in[17];
    const float* ws2 = (const float*)d_in[18]; const float* bs2 = (const float*)d_in[19];
    const float* wg  = (const float*)d_in[20]; const float* bg  = (const float*)d_in[21];
    const float* wh  = (const float*)d_in[22]; const float* bh  = (const float*)d_in[23];
    const float* wc1 = (const float*)d_in[24]; const float* bc1 = (const float*)d_in[25];
    const float* wc2 = (const float*)d_in[26]; const float* bc2 = (const float*)d_in[27];

    float* p_in  = symaddr(g_in);
    float* p_c1  = symaddr(g_c1);
    float* p_p1  = symaddr(g_p1);
    float* p_c2  = symaddr(g_c2);
    float* p_p2  = symaddr(g_p2);
    float* p_c3  = symaddr(g_c3);
    float* p_c4  = symaddr(g_c4);
    float* p_c5  = symaddr(g_c5);
    float* p_p5  = symaddr(g_p5);
    float* p_xc  = symaddr(g_xc);
    float* p_v   = symaddr(g_v);
    float* p_xh  = symaddr(g_xhat);
    float* p_nd  = symaddr(g_nodes);
    float* p_Y1  = symaddr(g_Y1);
    float* p_S   = symaddr(g_S);
    float* p_h1  = symaddr(g_h1);
    float* p_Y2  = symaddr(g_Y2);
    float* p_h2  = symaddr(g_h2);
    float* p_V1  = symaddr(g_V1);
    float* p_V1t = symaddr(g_V1t);
    float* p_Vx  = symaddr(g_Vx);
    float* p_G   = symaddr(g_G);
    float* p_Hh  = symaddr(g_Hh);
    float* p_A2  = symaddr(g_A2);
    float* p_xw  = symaddr(g_xw);
    float* p_c1m = symaddr(g_c1m);
    float* p_cw  = symaddr(g_cw);
    float* p_V2t = symaddr(g_V2t);

    // zero padded buffers (borders must be 0 every replay)
    cudaMemsetAsync(p_in, 0, sizeof(float) * ((size_t)N_IMG * 3 * H0P * W0P + TAILPAD), 0);
    cudaMemsetAsync(p_p1, 0, sizeof(float) * ((size_t)N_IMG * C1o * P1HP * P1WP + TAILPAD), 0);
    cudaMemsetAsync(p_p2, 0, sizeof(float) * ((size_t)N_IMG * C2o * P2HP * P2WP + TAILPAD), 0);
    cudaMemsetAsync(p_c3, 0, sizeof(float) * ((size_t)N_IMG * C3o * P2HP * P2WP + TAILPAD), 0);
    cudaMemsetAsync(p_c4, 0, sizeof(float) * ((size_t)N_IMG * C4o * P2HP * P2WP + TAILPAD), 0);

    // assemble padded input batch: exemplars first (0..15), search last (16)
    {
        int tot = 16 * 3 * H0 * W0;
        pad_copy_k<<<(tot + 127) / 128, 128>>>(exemplars, p_in, 16, 0);
        tot = 3 * H0 * W0;
        pad_copy_k<<<(tot + 127) / 128, 128>>>(search, p_in, 1, 16);
    }

    // ---- AlexNet features ----
    {   // conv1: 3->64, k11 s4
        int wq = (W1 + 3) / 4, sp = H1 * wq;
        conv4x4_k<3, 11, 4, 3><<<dim3((sp + 127) / 128, N_IMG * (C1o / 4)), 128>>>(
            p_in, aw1, ab1, p_c1, C1o, H0P, W0P, H1, W1, H1, W1, 0);
    }
    {   // pool1 -> padded2 buffer
        int tot = N_IMG * C1o * P1H * P1W;
        maxpool_k<<<(tot + 127) / 128, 128>>>(p_c1, p_p1, N_IMG * C1o, H1, W1, P1H, P1W, P1HP, P1WP, 2);
    }
    {   // conv2: 64->192, k5 s1
        int wq = (W2 + 3) / 4, sp = H2 * wq;
        conv4x4_k<64, 5, 1, 64><<<dim3((sp + 127) / 128, N_IMG * (C2o / 4)), 128>>>(
            p_p1, aw2, ab2, p_c2, C2o, P1HP, P1WP, H2, W2, H2, W2, 0);
    }
    {   // pool2 -> padded1 buffer
        int tot = N_IMG * C2o * P2H * P2W;
        maxpool_k<<<(tot + 127) / 128, 128>>>(p_c2, p_p2, N_IMG * C2o, H2, W2, P2H, P2W, P2HP, P2WP, 1);
    }
    {   // conv3: 192->384, out padded1
        int wq = (P2W + 3) / 4, sp = P2H * wq;
        conv4x4_k<192, 3, 1, 64><<<dim3((sp + 127) / 128, N_IMG * (C3o / 4)), 128>>>(
            p_p2, aw3, ab3, p_c3, C3o, P2HP, P2WP, P2H, P2W, P2HP, P2WP, 1);
    }
    {   // conv4: 384->256, out padded1
        int wq = (P2W + 3) / 4, sp = P2H * wq;
        conv4x4_k<384, 3, 1, 64><<<dim3((sp + 127) / 128, N_IMG * (C4o / 4)), 128>>>(
            p_c3, aw4, ab4, p_c4, C4o, P2HP, P2WP, P2H, P2W, P2HP, P2WP, 1);
    }
    {   // conv5: 256->256, out unpadded
        int wq = (P2W + 3) / 4, sp = P2H * wq;
        conv4x4_k<256, 3, 1, 64><<<dim3((sp + 127) / 128, N_IMG * (C5o / 4)), 128>>>(
            p_c4, aw5, ab5, p_c5, C5o, P2HP, P2WP, H5, W5, H5, W5, 0);
    }
    {   // pool5 -> [17,256,11,8]
        int tot = N_IMG * C5o * P5H * P5W;
        maxpool_k<<<(tot + 127) / 128, 128>>>(p_c5, p_p5, N_IMG * C5o, H5, W5, P5H, P5W, P5H, P5W, 0);
    }

    const float* Xf = p_p5 + (size_t)16 * 256 * 88;   // search features [256,88]

    // ---- conv_deconv branch ----
    cd_conv_k<<<88, 256>>>(Xf, wcd, bcd, p_xc);
    cd_max_k<<<1, 256>>>(p_xc, p_v);
    xhat_k<<<256, 88>>>(p_v, wt, bt, p_xh);

    // ---- spatiotemporal GCN ----
    gather_nodes_k<<<(TMN * 256 + 127) / 128, 128>>>(p_p5, p_nd);
    rbgemm_k<<<dim3(512 / 64, TMN / 64), 256>>>(p_nd, ws1, nullptr, p_Y1, TMN, 512, 256, 0);
    a1_reduce_k<<<dim3(4, 16), 128>>>(p_Y1, p_S, 512);
    a1_apply_k<<<(TMN * 512 + 255) / 256, 256>>>(p_Y1, p_S, bs1, p_h1, 512);
    rbgemm_k<<<dim3(256 / 64, TMN / 64), 256>>>(p_h1, ws2, nullptr, p_Y2, TMN, 256, 512, 0);
    a1_reduce_k<<<dim3(2, 16), 128>>>(p_Y2, p_S, 256);
    a1_apply_k<<<(TMN * 256 + 255) / 256, 256>>>(p_Y2, p_S, bs2, p_h2, 256);
    v1_k<<<(256 * 88 + 255) / 256, 256>>>(p_h2, p_xh, p_V1, p_V1t, p_Vx);

    // ---- dynamic cross-track graph ----
    rbgemm_k<<<dim3((88 + 63) / 64, 256 / 64), 256>>>(wg, p_Vx, bg, p_G, 256, 88, 256, 1);
    rbgemm_k<<<dim3((88 + 63) / 64, 256 / 64), 256>>>(wh, p_Vx, bh, p_Hh, 256, 88, 256, 1);
    attn_k<<<88, 128>>>(p_G, p_Hh, p_A2);

    // ---- ct GCN ----
    rbgemm_k<<<dim3(384 / 64, (88 + 63) / 64), 256>>>(p_V1t, wc1, nullptr, p_xw, 88, 384, 256, 0);
    rbgemm_k<<<dim3(384 / 64, (88 + 63) / 64), 256>>>(p_A2, p_xw, bc1, p_c1m, 88, 384, 88, 2 | 4);
    rbgemm_k<<<dim3(256 / 64, (88 + 63) / 64), 256>>>(p_c1m, wc2, nullptr, p_cw, 88, 256, 384, 0);
    rbgemm_k<<<dim3(256 / 64, (88 + 63) / 64), 256>>>(p_A2, p_cw, bc2, p_V2t, 88, 256, 88, 2 | 4);

    // ---- final correlation ----
    final_dot_k<<<1, 256>>>(Xf, p_V2t, (float*)d_out);
}